// round 8
// baseline (speedup 1.0000x reference)
#include <cuda_runtime.h>
#include <math.h>

#define D 128
#define K 8
#define TROWS 64
#define NTHREADS 256
#define LN_EPS 1e-5f
#define NORM_EPS 1e-12f

// packed dual-fp32 FMA (sm_100+): acc.{lo,hi} += a.{lo,hi} * b.{lo,hi}
#define FMA_F32X2(acc, a, b) \
    asm("fma.rn.f32x2 %0, %1, %2, %0;" : "+l"(acc) : "l"(a), "l"(b))

__global__ void __launch_bounds__(NTHREADS, 2)
l1q_kernel(const float* __restrict__ X, const float* __restrict__ W,
           const float* __restrict__ bias, const float* __restrict__ gamma,
           const float* __restrict__ beta, const float* __restrict__ cbk,
           float* __restrict__ out, int B, int ntiles)
{
    extern __shared__ float sm[];
    float* Ws  = sm;                 // D*D floats, swizzled k within row
    float* Xs  = Ws + D * D;         // TROWS*D
    float* CBs = Xs + TROWS * D;     // K*D raw codebook
    float* CBN = CBs + K * D;        // K*D normalized codebook
    float* Bv  = CBN + K * D;        // D
    float* Gv  = Bv + D;             // D
    float* BeV = Gv + D;             // D

    const int tid = threadIdx.x;
    const int tx  = tid & 31;
    const int wid = tid >> 5;        // 0..7

    // --- stage W: Ws[n*D + (k ^ ((n&7)<<2))] = W[n][k]
    // writes: per warp-row n fixed -> permuted contiguous 512B -> conflict-free
    // reads (mainloop): lanes vary n, 8 distinct 16B bank-chunks x4 -> 4 phases (full bw)
    for (int n = wid; n < D; n += 8) {
        float4 v = *(const float4*)&W[(size_t)n * D + 4 * tx];
        int ks = (4 * tx) ^ ((n & 7) << 2);
        *(float4*)&Ws[n * D + ks] = v;
    }
    if (tid < D) { Bv[tid] = bias[tid]; Gv[tid] = gamma[tid]; BeV[tid] = beta[tid]; }

    // --- codebook: warp `wid` normalizes row `wid` (K == 8 warps)
    {
        float v0 = cbk[wid * D + tx],      v1 = cbk[wid * D + tx + 32],
              v2 = cbk[wid * D + tx + 64], v3 = cbk[wid * D + tx + 96];
        float ss = v0 * v0 + v1 * v1 + v2 * v2 + v3 * v3;
        #pragma unroll
        for (int o = 16; o; o >>= 1) ss += __shfl_xor_sync(0xffffffffu, ss, o);
        float inv = 1.0f / fmaxf(sqrtf(ss), NORM_EPS);
        CBs[wid * D + tx]      = v0;  CBN[wid * D + tx]      = v0 * inv;
        CBs[wid * D + tx + 32] = v1;  CBN[wid * D + tx + 32] = v1 * inv;
        CBs[wid * D + tx + 64] = v2;  CBN[wid * D + tx + 64] = v2 * inv;
        CBs[wid * D + tx + 96] = v3;  CBN[wid * D + tx + 96] = v3 * inv;
    }

    const size_t oSoft = (size_t)B;                  // soft_assign  (B,K)
    const size_t oEmb  = (size_t)B * (1 + K);        // embedding    (B,D)
    const size_t oLog  = (size_t)B * (1 + K + D);    // logits       (B,K)
    const size_t totalX = (size_t)B * D;

    for (int tile = blockIdx.x; tile < ntiles; tile += gridDim.x) {
        const int rbase = tile * TROWS;
        __syncthreads();   // previous iteration done reading Xs
        for (int i = tid; i < TROWS * D / 4; i += NTHREADS) {
            size_t g = (size_t)rbase * D + (size_t)i * 4;
            float4 v = make_float4(0.f, 0.f, 0.f, 0.f);
            if (g + 3 < totalX) v = *(const float4*)&X[g];
            *(float4*)&Xs[i * 4] = v;
        }
        __syncthreads();

        // ---- GEMM: 8 rows x 4 cols per thread; acc = f32x2 over k parity
        unsigned long long acc[8][4];
        #pragma unroll
        for (int j = 0; j < 8; ++j)
            #pragma unroll
            for (int c = 0; c < 4; ++c) acc[j][c] = 0ull;

        const int r0 = wid * 8;
        #pragma unroll 4
        for (int k0 = 0; k0 < D; k0 += 4) {
            ulonglong2 wv[4];
            #pragma unroll
            for (int c = 0; c < 4; ++c) {
                int n = c * 32 + tx;
                wv[c] = *(const ulonglong2*)&Ws[n * D + (k0 ^ ((n & 7) << 2))];
            }
            #pragma unroll
            for (int j = 0; j < 8; ++j) {
                ulonglong2 xv = *(const ulonglong2*)&Xs[(r0 + j) * D + k0]; // warp-uniform: broadcast
                #pragma unroll
                for (int c = 0; c < 4; ++c) {
                    FMA_F32X2(acc[j][c], xv.x, wv[c].x);
                    FMA_F32X2(acc[j][c], xv.y, wv[c].y);
                }
            }
        }

        // ---- epilogue: each warp owns 8 complete rows
        #pragma unroll 1
        for (int j = 0; j < 8; ++j) {
            const int r = rbase + r0 + j;
            float hv[4];
            float s1 = 0.f, s2 = 0.f;
            #pragma unroll
            for (int c = 0; c < 4; ++c) {
                float lo = __uint_as_float((unsigned)(acc[j][c] & 0xffffffffull));
                float hi = __uint_as_float((unsigned)(acc[j][c] >> 32));
                int n = c * 32 + tx;
                float v = lo + hi + Bv[n];
                hv[c] = v;
                s1 += v;
                s2 += v * v;
            }
            #pragma unroll
            for (int o = 16; o; o >>= 1) {
                s1 += __shfl_xor_sync(0xffffffffu, s1, o);
                s2 += __shfl_xor_sync(0xffffffffu, s2, o);
            }
            float mu   = s1 * (1.0f / D);
            float var  = s2 * (1.0f / D) - mu * mu;
            float rstd = rsqrtf(var + LN_EPS);

            float s3 = 0.f;
            #pragma unroll
            for (int c = 0; c < 4; ++c) {
                int n = c * 32 + tx;
                float v = (hv[c] - mu) * rstd * Gv[n] + BeV[n];
                hv[c] = v;
                s3 += v * v;
            }
            #pragma unroll
            for (int o = 16; o; o >>= 1) s3 += __shfl_xor_sync(0xffffffffu, s3, o);
            float inv = 1.0f / fmaxf(sqrtf(s3), NORM_EPS);

            float lg[K];
            #pragma unroll
            for (int q = 0; q < K; ++q) {
                float p = 0.f;
                #pragma unroll
                for (int c = 0; c < 4; ++c) p += hv[c] * CBN[q * D + c * 32 + tx];
                lg[q] = p;
            }
            #pragma unroll
            for (int o = 16; o; o >>= 1) {
                #pragma unroll
                for (int q = 0; q < K; ++q)
                    lg[q] += __shfl_xor_sync(0xffffffffu, lg[q], o);
            }
            #pragma unroll
            for (int q = 0; q < K; ++q) lg[q] *= inv;   // TEMPERATURE == 1

            // argmax, first occurrence wins (matches jnp.argmax)
            float m = lg[0]; int bi = 0;
            #pragma unroll
            for (int q = 1; q < K; ++q) if (lg[q] > m) { m = lg[q]; bi = q; }

            float e[K], den = 0.f;
            #pragma unroll
            for (int q = 0; q < K; ++q) { e[q] = __expf(lg[q] - m); den += e[q]; }
            float rden = 1.0f / den;

            if (r < B) {
                if (tx == 0) out[r] = (float)bi;
                if (tx < K) {
                    out[oSoft + (size_t)r * K + tx] = e[tx] * rden;
                    out[oLog  + (size_t)r * K + tx] = lg[tx];
                }
                // straight-through: assign = onehot + soft - soft  -> (1+p)-p on the hot lane
                float pb = e[bi] * rden;
                float sc = (1.0f + pb) - pb;
                #pragma unroll
                for (int c = 0; c < 4; ++c) {
                    int n = c * 32 + tx;
                    out[oEmb + (size_t)r * D + n] = sc * CBs[bi * D + n];
                }
            }
        }
    }
}

extern "C" void kernel_launch(void* const* d_in, const int* in_sizes, int n_in,
                              void* d_out, int out_size)
{
    const float* X  = (const float*)d_in[0];
    const float* W  = (const float*)d_in[1];
    const float* b  = (const float*)d_in[2];
    const float* g  = (const float*)d_in[3];
    const float* be = (const float*)d_in[4];
    const float* cb = (const float*)d_in[5];

    int B = in_sizes[0] / D;
    int ntiles = (B + TROWS - 1) / TROWS;
    int smem = (D * D + TROWS * D + 2 * K * D + 3 * D) * (int)sizeof(float); // 108032 B

    cudaFuncSetAttribute(l1q_kernel, cudaFuncAttributeMaxDynamicSharedMemorySize, smem);

    int grid = ntiles < 304 ? ntiles : 304;   // persistent: 2 blocks/SM
    l1q_kernel<<<grid, NTHREADS, smem>>>(X, W, b, g, be, cb, (float*)d_out, B, ntiles);
}

// round 9
// speedup vs baseline: 1.0033x; 1.0033x over previous
#include <cuda_runtime.h>
#include <math.h>

#define D 128
#define K 8
#define TROWS 64
#define NTHREADS 256
#define LN_EPS 1e-5f
#define NORM_EPS 1e-12f

// packed dual-fp32 FMA (sm_100+): acc.{lo,hi} += a.{lo,hi} * b.{lo,hi}
#define FMA_F32X2(acc, a, b) \
    asm("fma.rn.f32x2 %0, %1, %2, %0;" : "+l"(acc) : "l"(a), "l"(b))

__global__ void __launch_bounds__(NTHREADS, 2)
l1q_kernel(const float* __restrict__ X, const float* __restrict__ W,
           const float* __restrict__ bias, const float* __restrict__ gamma,
           const float* __restrict__ beta, const float* __restrict__ cbk,
           float* __restrict__ out, int B, int ntiles)
{
    extern __shared__ float sm[];
    float* Ws  = sm;                 // D*D floats, swizzled k within row
    float* Xs  = Ws + D * D;         // TROWS*D
    float* CBs = Xs + TROWS * D;     // K*D raw codebook
    float* CBN = CBs + K * D;        // K*D normalized codebook
    float* Bv  = CBN + K * D;        // D
    float* Gv  = Bv + D;             // D
    float* BeV = Gv + D;             // D

    const int tid = threadIdx.x;
    const int tx  = tid & 31;
    const int wid = tid >> 5;        // 0..7

    // --- stage W: Ws[n*D + (k ^ ((n&7)<<2))] = W[n][k]
    // writes: per warp-row n fixed -> permuted contiguous 512B -> conflict-free
    // reads (mainloop): lanes vary n, 8 distinct 16B bank-chunks x4 -> 4 phases (full bw)
    for (int n = wid; n < D; n += 8) {
        float4 v = *(const float4*)&W[(size_t)n * D + 4 * tx];
        int ks = (4 * tx) ^ ((n & 7) << 2);
        *(float4*)&Ws[n * D + ks] = v;
    }
    if (tid < D) { Bv[tid] = bias[tid]; Gv[tid] = gamma[tid]; BeV[tid] = beta[tid]; }

    // --- codebook: warp `wid` normalizes row `wid` (K == 8 warps)
    {
        float v0 = cbk[wid * D + tx],      v1 = cbk[wid * D + tx + 32],
              v2 = cbk[wid * D + tx + 64], v3 = cbk[wid * D + tx + 96];
        float ss = v0 * v0 + v1 * v1 + v2 * v2 + v3 * v3;
        #pragma unroll
        for (int o = 16; o; o >>= 1) ss += __shfl_xor_sync(0xffffffffu, ss, o);
        float inv = 1.0f / fmaxf(sqrtf(ss), NORM_EPS);
        CBs[wid * D + tx]      = v0;  CBN[wid * D + tx]      = v0 * inv;
        CBs[wid * D + tx + 32] = v1;  CBN[wid * D + tx + 32] = v1 * inv;
        CBs[wid * D + tx + 64] = v2;  CBN[wid * D + tx + 64] = v2 * inv;
        CBs[wid * D + tx + 96] = v3;  CBN[wid * D + tx + 96] = v3 * inv;
    }

    const size_t oSoft = (size_t)B;                  // soft_assign  (B,K)
    const size_t oEmb  = (size_t)B * (1 + K);        // embedding    (B,D)
    const size_t oLog  = (size_t)B * (1 + K + D);    // logits       (B,K)
    const size_t totalX = (size_t)B * D;

    for (int tile = blockIdx.x; tile < ntiles; tile += gridDim.x) {
        const int rbase = tile * TROWS;
        __syncthreads();   // previous iteration done reading Xs
        for (int i = tid; i < TROWS * D / 4; i += NTHREADS) {
            size_t g = (size_t)rbase * D + (size_t)i * 4;
            float4 v = make_float4(0.f, 0.f, 0.f, 0.f);
            if (g + 3 < totalX) v = *(const float4*)&X[g];
            *(float4*)&Xs[i * 4] = v;
        }
        __syncthreads();

        // ---- GEMM: 8 rows x 4 cols per thread; acc = f32x2 over k parity
        unsigned long long acc[8][4];
        #pragma unroll
        for (int j = 0; j < 8; ++j)
            #pragma unroll
            for (int c = 0; c < 4; ++c) acc[j][c] = 0ull;

        const int r0 = wid * 8;
        #pragma unroll 4
        for (int k0 = 0; k0 < D; k0 += 4) {
            ulonglong2 wv[4];
            #pragma unroll
            for (int c = 0; c < 4; ++c) {
                int n = c * 32 + tx;
                wv[c] = *(const ulonglong2*)&Ws[n * D + (k0 ^ ((n & 7) << 2))];
            }
            #pragma unroll
            for (int j = 0; j < 8; ++j) {
                ulonglong2 xv = *(const ulonglong2*)&Xs[(r0 + j) * D + k0]; // warp-uniform: broadcast
                #pragma unroll
                for (int c = 0; c < 4; ++c) {
                    FMA_F32X2(acc[j][c], xv.x, wv[c].x);
                    FMA_F32X2(acc[j][c], xv.y, wv[c].y);
                }
            }
        }

        // ---- epilogue: each warp owns 8 complete rows
        #pragma unroll 1
        for (int j = 0; j < 8; ++j) {
            const int r = rbase + r0 + j;
            float hv[4];
            float s1 = 0.f, s2 = 0.f;
            #pragma unroll
            for (int c = 0; c < 4; ++c) {
                float lo = __uint_as_float((unsigned)(acc[j][c] & 0xffffffffull));
                float hi = __uint_as_float((unsigned)(acc[j][c] >> 32));
                int n = c * 32 + tx;
                float v = lo + hi + Bv[n];
                hv[c] = v;
                s1 += v;
                s2 += v * v;
            }
            #pragma unroll
            for (int o = 16; o; o >>= 1) {
                s1 += __shfl_xor_sync(0xffffffffu, s1, o);
                s2 += __shfl_xor_sync(0xffffffffu, s2, o);
            }
            float mu   = s1 * (1.0f / D);
            float var  = s2 * (1.0f / D) - mu * mu;
            float rstd = rsqrtf(var + LN_EPS);

            float s3 = 0.f;
            #pragma unroll
            for (int c = 0; c < 4; ++c) {
                int n = c * 32 + tx;
                float v = (hv[c] - mu) * rstd * Gv[n] + BeV[n];
                hv[c] = v;
                s3 += v * v;
            }
            #pragma unroll
            for (int o = 16; o; o >>= 1) s3 += __shfl_xor_sync(0xffffffffu, s3, o);
            float inv = 1.0f / fmaxf(sqrtf(s3), NORM_EPS);

            float lg[K];
            #pragma unroll
            for (int q = 0; q < K; ++q) {
                float p = 0.f;
                #pragma unroll
                for (int c = 0; c < 4; ++c) p += hv[c] * CBN[q * D + c * 32 + tx];
                lg[q] = p;
            }
            #pragma unroll
            for (int o = 16; o; o >>= 1) {
                #pragma unroll
                for (int q = 0; q < K; ++q)
                    lg[q] += __shfl_xor_sync(0xffffffffu, lg[q], o);
            }
            #pragma unroll
            for (int q = 0; q < K; ++q) lg[q] *= inv;   // TEMPERATURE == 1

            // argmax, first occurrence wins (matches jnp.argmax)
            float m = lg[0]; int bi = 0;
            #pragma unroll
            for (int q = 1; q < K; ++q) if (lg[q] > m) { m = lg[q]; bi = q; }

            float e[K], den = 0.f;
            #pragma unroll
            for (int q = 0; q < K; ++q) { e[q] = __expf(lg[q] - m); den += e[q]; }
            float rden = 1.0f / den;

            if (r < B) {
                if (tx == 0) out[r] = (float)bi;
                if (tx < K) {
                    out[oSoft + (size_t)r * K + tx] = e[tx] * rden;
                    out[oLog  + (size_t)r * K + tx] = lg[tx];
                }
                // straight-through: assign = onehot + soft - soft  -> (1+p)-p on the hot lane
                float pb = e[bi] * rden;
                float sc = (1.0f + pb) - pb;
                #pragma unroll
                for (int c = 0; c < 4; ++c) {
                    int n = c * 32 + tx;
                    out[oEmb + (size_t)r * D + n] = sc * CBs[bi * D + n];
                }
            }
        }
    }
}

extern "C" void kernel_launch(void* const* d_in, const int* in_sizes, int n_in,
                              void* d_out, int out_size)
{
    const float* X  = (const float*)d_in[0];
    const float* W  = (const float*)d_in[1];
    const float* b  = (const float*)d_in[2];
    const float* g  = (const float*)d_in[3];
    const float* be = (const float*)d_in[4];
    const float* cb = (const float*)d_in[5];

    int B = in_sizes[0] / D;
    int ntiles = (B + TROWS - 1) / TROWS;
    int smem = (D * D + TROWS * D + 2 * K * D + 3 * D) * (int)sizeof(float); // 108032 B

    cudaFuncSetAttribute(l1q_kernel, cudaFuncAttributeMaxDynamicSharedMemorySize, smem);

    int grid = ntiles < 304 ? ntiles : 304;   // persistent: 2 blocks/SM
    l1q_kernel<<<grid, NTHREADS, smem>>>(X, W, b, g, be, cb, (float*)d_out, B, ntiles);
}